// round 2
// baseline (speedup 1.0000x reference)
#include <cuda_runtime.h>

// Problem constants
#define BB     1024
#define TT     2048
#define DD     5
#define HH     64
#define GG     256     // 4*H gates
#define OUTN   128
#define BTILE  8
#define THREADS 256
#define NCTA   (BB/BTILE)

// Shared memory layout (bytes)
#define OFF_W1   0                       // float2[32][256]  Whh0 k-pairs        65536
#define OFF_W2   65536                   // float2[64][256]  [Wih1|Whh1] k-pairs 131072
#define OFF_WX   196608                  // float [5][256]   Wih0 transposed      5120
#define OFF_HC   201728                  // float2[64][8]    [h1;h2] k-pairs      4096
#define OFF_ACT  205824                  // float [4][64][8] activations          8192
#define OFF_XB   214016                  // float [2][5][8]  x double buffer       320
#define SMEM_BYTES 214336

// Scratch for final h2 (allocation-free: device global)
__device__ float g_h2[BB * HH];

__device__ __forceinline__ unsigned long long ffma2(unsigned long long a,
                                                    unsigned long long b,
                                                    unsigned long long c) {
    unsigned long long d;
    asm("fma.rn.f32x2 %0, %1, %2, %3;" : "=l"(d) : "l"(a), "l"(b), "l"(c));
    return d;
}

__device__ __forceinline__ float sigf(float x) {
    return __fdividef(1.0f, 1.0f + __expf(-x));
}
__device__ __forceinline__ float tanh_fast(float x) {
    return __fdividef(2.0f, 1.0f + __expf(-2.0f * x)) - 1.0f;
}

__global__ void __launch_bounds__(THREADS, 1)
lstm_fused_kernel(const float* __restrict__ x,
                  const float* __restrict__ Wih0, const float* __restrict__ Whh0,
                  const float* __restrict__ bih0, const float* __restrict__ bhh0,
                  const float* __restrict__ Wih1, const float* __restrict__ Whh1,
                  const float* __restrict__ bih1, const float* __restrict__ bhh1)
{
    extern __shared__ char smem[];
    float2*       W1f = (float2*)(smem + OFF_W1);
    float2*       W2f = (float2*)(smem + OFF_W2);
    float*        WX  = (float*) (smem + OFF_WX);
    float*        HCf = (float*) (smem + OFF_HC);
    float*        ACT = (float*) (smem + OFF_ACT);
    float*        XB  = (float*) (smem + OFF_XB);
    const unsigned long long* W1u = (const unsigned long long*)(smem + OFF_W1);
    const unsigned long long* W2u = (const unsigned long long*)(smem + OFF_W2);
    const ulonglong2*         HCu = (const ulonglong2*)        (smem + OFF_HC);

    const int tid = threadIdx.x;
    const int b0  = blockIdx.x * BTILE;

    // ---- Stage weights into SMEM (one time; reused for all 2048 steps) ----
    // W1f[kp][g] = (Whh0[g][2kp], Whh0[g][2kp+1])
    for (int i = tid; i < GG * (HH / 2); i += THREADS) {
        int g = i >> 5, kp = i & 31;
        W1f[kp * GG + g] = ((const float2*)Whh0)[i];
    }
    // W2f[kp][g]: kp<32 -> Wih1 pairs, kp>=32 -> Whh1 pairs
    for (int i = tid; i < GG * HH; i += THREADS) {
        int g = i >> 6, kp = i & 63;
        float2 v = (kp < 32) ? ((const float2*)Wih1)[g * 32 + kp]
                             : ((const float2*)Whh1)[g * 32 + kp - 32];
        W2f[kp * GG + g] = v;
    }
    // WX[d][g] = Wih0[g][d]
    for (int i = tid; i < GG * DD; i += THREADS) {
        int g = i / DD, d = i - g * DD;
        WX[d * GG + g] = Wih0[i];
    }
    // zero hidden state (h1, h2)
    for (int i = tid; i < HH * BTILE * 2; i += THREADS) HCf[i] = 0.0f;

    const float breg1 = bih0[tid] + bhh0[tid];
    const float breg2 = bih1[tid] + bhh1[tid];

    // initial x staging for t=0
    const int bb = tid / DD, dd = tid - (tid / DD) * DD;
    if (tid < DD * BTILE) {
        XB[dd * 8 + bb] = x[((size_t)(b0 + bb) * TT + 0) * DD + dd];
    }
    __syncthreads();

    // per-thread cell state (updater mapping: unit uu, batch pair ub,ub+1)
    float2 c1 = make_float2(0.f, 0.f);
    float2 c2 = make_float2(0.f, 0.f);
    const int uu   = tid >> 2;
    const int ub   = (tid & 3) * 2;
    const int aof  = uu * 8 + ub;                        // activation read offset
    const int hco1 = (uu >> 1) * 16 + ub * 2 + (uu & 1); // h1 write offset
    const int hco2 = 512 + hco1;                         // h2 write offset
    const bool isg = (tid >= 128) && (tid < 192);        // 'g' gate -> tanh

    for (int t = 0; t < TT; ++t) {
        const int cur = t & 1, nxt = cur ^ 1;

        // prefetch next-step x into registers (hidden behind layer-1 GEMV)
        float xpre = 0.0f;
        if (tid < DD * BTILE) {
            int tn = (t + 1 < TT) ? (t + 1) : t;
            xpre = x[((size_t)(b0 + bb) * TT + tn) * DD + dd];
        }

        // ================= Layer 1 gates: g = tid =================
        float sx[BTILE];
        #pragma unroll
        for (int b = 0; b < BTILE; b++) sx[b] = breg1;
        const float* xrow = XB + cur * 40;
        #pragma unroll
        for (int d = 0; d < DD; d++) {
            float  w  = WX[d * GG + tid];
            float4 xa = *(const float4*)(xrow + d * 8);
            float4 xc = *(const float4*)(xrow + d * 8 + 4);
            sx[0] += w * xa.x; sx[1] += w * xa.y; sx[2] += w * xa.z; sx[3] += w * xa.w;
            sx[4] += w * xc.x; sx[5] += w * xc.y; sx[6] += w * xc.z; sx[7] += w * xc.w;
        }
        unsigned long long acc[BTILE];
        #pragma unroll
        for (int b = 0; b < BTILE; b++)
            acc[b] = (unsigned long long)__float_as_uint(sx[b]);   // (bias+x, 0)

        #pragma unroll 4
        for (int kp = 0; kp < 32; kp++) {
            unsigned long long w = W1u[kp * GG + tid];
            ulonglong2 h01 = HCu[kp * 4 + 0];
            ulonglong2 h23 = HCu[kp * 4 + 1];
            ulonglong2 h45 = HCu[kp * 4 + 2];
            ulonglong2 h67 = HCu[kp * 4 + 3];
            acc[0] = ffma2(w, h01.x, acc[0]); acc[1] = ffma2(w, h01.y, acc[1]);
            acc[2] = ffma2(w, h23.x, acc[2]); acc[3] = ffma2(w, h23.y, acc[3]);
            acc[4] = ffma2(w, h45.x, acc[4]); acc[5] = ffma2(w, h45.y, acc[5]);
            acc[6] = ffma2(w, h67.x, acc[6]); acc[7] = ffma2(w, h67.y, acc[7]);
        }
        {
            float av[BTILE];
            #pragma unroll
            for (int b = 0; b < BTILE; b++) {
                float v = __uint_as_float((unsigned)acc[b]) +
                          __uint_as_float((unsigned)(acc[b] >> 32));
                av[b] = isg ? tanh_fast(v) : sigf(v);
            }
            *(float4*)(ACT + tid * 8)     = make_float4(av[0], av[1], av[2], av[3]);
            *(float4*)(ACT + tid * 8 + 4) = make_float4(av[4], av[5], av[6], av[7]);
        }
        // stage next x (double buffered, no conflict with current readers)
        if (tid < DD * BTILE) XB[nxt * 40 + dd * 8 + bb] = xpre;
        __syncthreads();

        // ================= Layer 1 cell/hidden update =================
        {
            float2 ai = *(const float2*)(ACT + aof);
            float2 af = *(const float2*)(ACT + 512 + aof);
            float2 ag = *(const float2*)(ACT + 1024 + aof);
            float2 ao = *(const float2*)(ACT + 1536 + aof);
            c1.x = af.x * c1.x + ai.x * ag.x;
            c1.y = af.y * c1.y + ai.y * ag.y;
            HCf[hco1]     = ao.x * tanh_fast(c1.x);
            HCf[hco1 + 2] = ao.y * tanh_fast(c1.y);
        }
        __syncthreads();

        // ================= Layer 2 gates (k = [h1; h2_prev], 128) =================
        #pragma unroll
        for (int b = 0; b < BTILE; b++)
            acc[b] = (unsigned long long)__float_as_uint(breg2);

        #pragma unroll 4
        for (int kp = 0; kp < 64; kp++) {
            unsigned long long w = W2u[kp * GG + tid];
            ulonglong2 h01 = HCu[kp * 4 + 0];
            ulonglong2 h23 = HCu[kp * 4 + 1];
            ulonglong2 h45 = HCu[kp * 4 + 2];
            ulonglong2 h67 = HCu[kp * 4 + 3];
            acc[0] = ffma2(w, h01.x, acc[0]); acc[1] = ffma2(w, h01.y, acc[1]);
            acc[2] = ffma2(w, h23.x, acc[2]); acc[3] = ffma2(w, h23.y, acc[3]);
            acc[4] = ffma2(w, h45.x, acc[4]); acc[5] = ffma2(w, h45.y, acc[5]);
            acc[6] = ffma2(w, h67.x, acc[6]); acc[7] = ffma2(w, h67.y, acc[7]);
        }
        {
            float av[BTILE];
            #pragma unroll
            for (int b = 0; b < BTILE; b++) {
                float v = __uint_as_float((unsigned)acc[b]) +
                          __uint_as_float((unsigned)(acc[b] >> 32));
                av[b] = isg ? tanh_fast(v) : sigf(v);
            }
            *(float4*)(ACT + tid * 8)     = make_float4(av[0], av[1], av[2], av[3]);
            *(float4*)(ACT + tid * 8 + 4) = make_float4(av[4], av[5], av[6], av[7]);
        }
        __syncthreads();

        // ================= Layer 2 cell/hidden update =================
        {
            float2 ai = *(const float2*)(ACT + aof);
            float2 af = *(const float2*)(ACT + 512 + aof);
            float2 ag = *(const float2*)(ACT + 1024 + aof);
            float2 ao = *(const float2*)(ACT + 1536 + aof);
            c2.x = af.x * c2.x + ai.x * ag.x;
            c2.y = af.y * c2.y + ai.y * ag.y;
            HCf[hco2]     = ao.x * tanh_fast(c2.x);
            HCf[hco2 + 2] = ao.y * tanh_fast(c2.y);
        }
        __syncthreads();
    }

    // write final h2 to global scratch
    for (int j = tid; j < HH * BTILE; j += THREADS) {
        int u = j >> 3, b = j & 7;
        g_h2[(size_t)(b0 + b) * HH + u] = HCf[512 + (u >> 1) * 16 + b * 2 + (u & 1)];
    }
}

// out[b][o] = relu(sum_u h2[b][u] * Wfc[o][u] + bfc[o])
__global__ void __launch_bounds__(256)
fc_relu_kernel(const float* __restrict__ Wfc, const float* __restrict__ bfc,
               float* __restrict__ out)
{
    int gid = blockIdx.x * 256 + threadIdx.x;   // 0 .. B*OUT-1
    int b = gid >> 7;
    int o = gid & (OUTN - 1);
    const float* hv = g_h2 + (size_t)b * HH;
    const float* wr = Wfc + (size_t)o * HH;
    float s = bfc[o];
    #pragma unroll
    for (int u = 0; u < HH; u += 4) {
        float4 h4 = *(const float4*)(hv + u);
        float4 w4 = *(const float4*)(wr + u);
        s += h4.x * w4.x + h4.y * w4.y + h4.z * w4.z + h4.w * w4.w;
    }
    out[gid] = fmaxf(s, 0.0f);
}

extern "C" void kernel_launch(void* const* d_in, const int* in_sizes, int n_in,
                              void* d_out, int out_size)
{
    const float* x    = (const float*)d_in[0];
    const float* Wih0 = (const float*)d_in[1];
    const float* Whh0 = (const float*)d_in[2];
    const float* bih0 = (const float*)d_in[3];
    const float* bhh0 = (const float*)d_in[4];
    const float* Wih1 = (const float*)d_in[5];
    const float* Whh1 = (const float*)d_in[6];
    const float* bih1 = (const float*)d_in[7];
    const float* bhh1 = (const float*)d_in[8];
    const float* Wfc  = (const float*)d_in[9];
    const float* bfc  = (const float*)d_in[10];
    float* out = (float*)d_out;

    cudaFuncSetAttribute(lstm_fused_kernel,
                         cudaFuncAttributeMaxDynamicSharedMemorySize, SMEM_BYTES);

    lstm_fused_kernel<<<NCTA, THREADS, SMEM_BYTES>>>(
        x, Wih0, Whh0, bih0, bhh0, Wih1, Whh1, bih1, bhh1);

    fc_relu_kernel<<<(BB * OUTN) / 256, 256>>>(Wfc, bfc, out);
}

// round 3
// speedup vs baseline: 1.1295x; 1.1295x over previous
#include <cuda_runtime.h>

// Problem constants
#define BB     1024
#define TT     2048
#define DD     5
#define HH     64
#define GG     256     // 4*H gates
#define OUTN   128
#define BTILE  8
#define THREADS 256
#define NCTA   (BB/BTILE)

// Shared memory layout (bytes)
#define OFF_W1    0                      // float2[32][256]  Whh0 k-pairs       65536
#define OFF_WX    65536                  // float [5][256]   Wih0 transposed     5120
#define OFF_HC    70656                  // float2[64][8]    [h1;h2] k-pairs     4096
#define OFF_ACT1  74752                  // float [4][64][8] layer-1 acts        8192
#define OFF_ACT2  82944                  // float [4][64][8] layer-2 acts        8192
#define OFF_XB    91136                  // float [2][5][8]  x double buffer      320
#define SMEM_BYTES 91456

__device__ __forceinline__ unsigned long long ffma2(unsigned long long a,
                                                    unsigned long long b,
                                                    unsigned long long c) {
    unsigned long long d;
    asm("fma.rn.f32x2 %0, %1, %2, %3;" : "=l"(d) : "l"(a), "l"(b), "l"(c));
    return d;
}

__device__ __forceinline__ float sigf(float x) {
    return __fdividef(1.0f, 1.0f + __expf(-x));
}
__device__ __forceinline__ float tanh_fast(float x) {
    return __fdividef(2.0f, 1.0f + __expf(-2.0f * x)) - 1.0f;
}

__global__ void __launch_bounds__(THREADS, 1)
lstm_fused_kernel(const float* __restrict__ x,
                  const float* __restrict__ Wih0, const float* __restrict__ Whh0,
                  const float* __restrict__ bih0, const float* __restrict__ bhh0,
                  const float* __restrict__ Wih1, const float* __restrict__ Whh1,
                  const float* __restrict__ bih1, const float* __restrict__ bhh1,
                  const float* __restrict__ Wfc,  const float* __restrict__ bfc,
                  float* __restrict__ out)
{
    extern __shared__ char smem[];
    float2*       W1f  = (float2*)(smem + OFF_W1);
    float*        WX   = (float*) (smem + OFF_WX);
    float*        HCf  = (float*) (smem + OFF_HC);
    float*        ACT1 = (float*) (smem + OFF_ACT1);
    float*        ACT2 = (float*) (smem + OFF_ACT2);
    float*        XB   = (float*) (smem + OFF_XB);
    const unsigned long long* W1u = (const unsigned long long*)(smem + OFF_W1);
    const ulonglong2*         HCu = (const ulonglong2*)        (smem + OFF_HC);

    const int tid = threadIdx.x;
    const int b0  = blockIdx.x * BTILE;

    // ---- Layer-2 weights for this thread's gate -> REGISTERS ----
    // w2r[kp<32]  = (Wih1[g][2kp], Wih1[g][2kp+1])   (input = h1)
    // w2r[kp>=32] = (Whh1[g][2(kp-32)], ...)          (recurrent = h2)
    unsigned long long w2r[64];
    {
        const unsigned long long* wi = (const unsigned long long*)(Wih1 + (size_t)tid * HH);
        const unsigned long long* wh = (const unsigned long long*)(Whh1 + (size_t)tid * HH);
        #pragma unroll
        for (int k = 0; k < 32; k++) w2r[k]      = wi[k];
        #pragma unroll
        for (int k = 0; k < 32; k++) w2r[32 + k] = wh[k];
    }

    // ---- Stage layer-1 weights into SMEM ----
    for (int i = tid; i < GG * (HH / 2); i += THREADS) {
        int g = i >> 5, kp = i & 31;
        W1f[kp * GG + g] = ((const float2*)Whh0)[i];
    }
    for (int i = tid; i < GG * DD; i += THREADS) {
        int g = i / DD, d = i - g * DD;
        WX[d * GG + g] = Wih0[i];
    }
    for (int i = tid; i < HH * BTILE * 2; i += THREADS) HCf[i] = 0.0f;

    const float breg1 = bih0[tid] + bhh0[tid];
    const float breg2 = bih1[tid] + bhh1[tid];

    // initial x staging for t=0
    const int bb = tid / DD, dd = tid - (tid / DD) * DD;
    if (tid < DD * BTILE) {
        XB[dd * 8 + bb] = x[((size_t)(b0 + bb) * TT + 0) * DD + dd];
    }
    __syncthreads();

    // per-thread cell state (updater mapping: unit uu, batch pair ub,ub+1)
    float2 c1 = make_float2(0.f, 0.f);
    float2 c2 = make_float2(0.f, 0.f);
    const int uu   = tid >> 2;
    const int ub   = (tid & 3) * 2;
    const int aof  = uu * 8 + ub;                        // activation read offset
    const int hco1 = (uu >> 1) * 16 + ub * 2 + (uu & 1); // h1 write offset
    const int hco2 = 512 + hco1;                         // h2 write offset
    const bool isg = (tid >= 128) && (tid < 192);        // 'g' gate -> tanh

    for (int t = 0; t < TT; ++t) {
        const int cur = t & 1, nxt = cur ^ 1;

        // prefetch next-step x into registers (hidden behind layer-1 GEMV)
        float xpre = 0.0f;
        if (tid < DD * BTILE) {
            int tn = (t + 1 < TT) ? (t + 1) : t;
            xpre = x[((size_t)(b0 + bb) * TT + tn) * DD + dd];
        }

        // ========= Phase A: Layer-1 gates (g = tid), write ACT1 =========
        float sx[BTILE];
        #pragma unroll
        for (int b = 0; b < BTILE; b++) sx[b] = breg1;
        const float* xrow = XB + cur * 40;
        #pragma unroll
        for (int d = 0; d < DD; d++) {
            float  w  = WX[d * GG + tid];
            float4 xa = *(const float4*)(xrow + d * 8);
            float4 xc = *(const float4*)(xrow + d * 8 + 4);
            sx[0] += w * xa.x; sx[1] += w * xa.y; sx[2] += w * xa.z; sx[3] += w * xa.w;
            sx[4] += w * xc.x; sx[5] += w * xc.y; sx[6] += w * xc.z; sx[7] += w * xc.w;
        }
        unsigned long long acc[BTILE];
        #pragma unroll
        for (int b = 0; b < BTILE; b++)
            acc[b] = (unsigned long long)__float_as_uint(sx[b]);   // (bias+x, 0)

        #pragma unroll 8
        for (int kp = 0; kp < 32; kp++) {
            unsigned long long w = W1u[kp * GG + tid];
            ulonglong2 h01 = HCu[kp * 4 + 0];
            ulonglong2 h23 = HCu[kp * 4 + 1];
            ulonglong2 h45 = HCu[kp * 4 + 2];
            ulonglong2 h67 = HCu[kp * 4 + 3];
            acc[0] = ffma2(w, h01.x, acc[0]); acc[1] = ffma2(w, h01.y, acc[1]);
            acc[2] = ffma2(w, h23.x, acc[2]); acc[3] = ffma2(w, h23.y, acc[3]);
            acc[4] = ffma2(w, h45.x, acc[4]); acc[5] = ffma2(w, h45.y, acc[5]);
            acc[6] = ffma2(w, h67.x, acc[6]); acc[7] = ffma2(w, h67.y, acc[7]);
        }
        {
            float av[BTILE];
            #pragma unroll
            for (int b = 0; b < BTILE; b++) {
                float v = __uint_as_float((unsigned)acc[b]) +
                          __uint_as_float((unsigned)(acc[b] >> 32));
                av[b] = isg ? tanh_fast(v) : sigf(v);
            }
            *(float4*)(ACT1 + tid * 8)     = make_float4(av[0], av[1], av[2], av[3]);
            *(float4*)(ACT1 + tid * 8 + 4) = make_float4(av[4], av[5], av[6], av[7]);
        }
        if (tid < DD * BTILE) XB[nxt * 40 + dd * 8 + bb] = xpre;
        __syncthreads();   // bar 1

        // ========= Phase B: Layer-1 cell/hidden update =========
        {
            float2 ai = *(const float2*)(ACT1 + aof);
            float2 af = *(const float2*)(ACT1 + 512 + aof);
            float2 ag = *(const float2*)(ACT1 + 1024 + aof);
            float2 ao = *(const float2*)(ACT1 + 1536 + aof);
            c1.x = af.x * c1.x + ai.x * ag.x;
            c1.y = af.y * c1.y + ai.y * ag.y;
            HCf[hco1]     = ao.x * tanh_fast(c1.x);
            HCf[hco1 + 2] = ao.y * tanh_fast(c1.y);
        }
        __syncthreads();   // bar 2

        // ========= Phase C: Layer-2 gates (k = [h1; h2_prev], 128) =========
        #pragma unroll
        for (int b = 0; b < BTILE; b++)
            acc[b] = (unsigned long long)__float_as_uint(breg2);

        #pragma unroll
        for (int kp = 0; kp < 64; kp++) {
            unsigned long long w = w2r[kp];
            ulonglong2 h01 = HCu[kp * 4 + 0];
            ulonglong2 h23 = HCu[kp * 4 + 1];
            ulonglong2 h45 = HCu[kp * 4 + 2];
            ulonglong2 h67 = HCu[kp * 4 + 3];
            acc[0] = ffma2(w, h01.x, acc[0]); acc[1] = ffma2(w, h01.y, acc[1]);
            acc[2] = ffma2(w, h23.x, acc[2]); acc[3] = ffma2(w, h23.y, acc[3]);
            acc[4] = ffma2(w, h45.x, acc[4]); acc[5] = ffma2(w, h45.y, acc[5]);
            acc[6] = ffma2(w, h67.x, acc[6]); acc[7] = ffma2(w, h67.y, acc[7]);
        }
        {
            float av[BTILE];
            #pragma unroll
            for (int b = 0; b < BTILE; b++) {
                float v = __uint_as_float((unsigned)acc[b]) +
                          __uint_as_float((unsigned)(acc[b] >> 32));
                av[b] = isg ? tanh_fast(v) : sigf(v);
            }
            *(float4*)(ACT2 + tid * 8)     = make_float4(av[0], av[1], av[2], av[3]);
            *(float4*)(ACT2 + tid * 8 + 4) = make_float4(av[4], av[5], av[6], av[7]);
        }
        __syncthreads();   // bar 3

        // ========= Phase D: Layer-2 cell/hidden update (no bar; folds into bar 1) =========
        {
            float2 ai = *(const float2*)(ACT2 + aof);
            float2 af = *(const float2*)(ACT2 + 512 + aof);
            float2 ag = *(const float2*)(ACT2 + 1024 + aof);
            float2 ao = *(const float2*)(ACT2 + 1536 + aof);
            c2.x = af.x * c2.x + ai.x * ag.x;
            c2.y = af.y * c2.y + ai.y * ag.y;
            HCf[hco2]     = ao.x * tanh_fast(c2.x);
            HCf[hco2 + 2] = ao.y * tanh_fast(c2.y);
        }
    }
    __syncthreads();

    // ========= Fused FC + ReLU: out[b][o] = relu(h2[b] . Wfc[o] + bfc[o]) =========
    // thread t: batch b = t>>5 (warp-uniform), outputs o = (t&31)*4 .. +3
    {
        const int b  = tid >> 5;
        const int o  = (tid & 31) * 4;
        const float* w0 = Wfc + (size_t)(o + 0) * HH;
        const float* w1 = Wfc + (size_t)(o + 1) * HH;
        const float* w2 = Wfc + (size_t)(o + 2) * HH;
        const float* w3 = Wfc + (size_t)(o + 3) * HH;
        float s0 = bfc[o], s1 = bfc[o + 1], s2 = bfc[o + 2], s3 = bfc[o + 3];
        #pragma unroll
        for (int u = 0; u < HH; u++) {
            float h = HCf[512 + (u >> 1) * 16 + b * 2 + (u & 1)];
            s0 += h * w0[u]; s1 += h * w1[u]; s2 += h * w2[u]; s3 += h * w3[u];
        }
        float4 r = make_float4(fmaxf(s0, 0.f), fmaxf(s1, 0.f),
                               fmaxf(s2, 0.f), fmaxf(s3, 0.f));
        *(float4*)(out + (size_t)(b0 + b) * OUTN + o) = r;
    }
}

extern "C" void kernel_launch(void* const* d_in, const int* in_sizes, int n_in,
                              void* d_out, int out_size)
{
    const float* x    = (const float*)d_in[0];
    const float* Wih0 = (const float*)d_in[1];
    const float* Whh0 = (const float*)d_in[2];
    const float* bih0 = (const float*)d_in[3];
    const float* bhh0 = (const float*)d_in[4];
    const float* Wih1 = (const float*)d_in[5];
    const float* Whh1 = (const float*)d_in[6];
    const float* bih1 = (const float*)d_in[7];
    const float* bhh1 = (const float*)d_in[8];
    const float* Wfc  = (const float*)d_in[9];
    const float* bfc  = (const float*)d_in[10];
    float* out = (float*)d_out;

    cudaFuncSetAttribute(lstm_fused_kernel,
                         cudaFuncAttributeMaxDynamicSharedMemorySize, SMEM_BYTES);

    lstm_fused_kernel<<<NCTA, THREADS, SMEM_BYTES>>>(
        x, Wih0, Whh0, bih0, bhh0, Wih1, Whh1, bih1, bhh1, Wfc, bfc, out);
}

// round 11
// speedup vs baseline: 1.4148x; 1.2526x over previous
#include <cuda_runtime.h>

// Problem constants
#define BB     1024
#define TT     2048
#define DD     5
#define HH     64
#define GG     256     // 4*H gates
#define OUTN   128
#define BTILE  7
#define THREADS 512
#define NCTA   147     // 147*7 = 1029 >= 1024 (last CTA: 2 valid, 5 dummy)

// Shared memory layout (bytes)
#define OFF_W1    0                 // float2[32][256]  Whh0 k-pairs          65536
#define OFF_WX    65536             // float [5][256]   Wih0 transposed        5120
#define OFF_HC    70656             // float2[64][8]    kp0-31: h1, kp32-63: h2 4096
#define OFF_PA    74752             // float[2][2 chunks][1040] layer-1 partials 16640
#define OFF_PB    91392             // same for layer-2                       16640
#define OFF_XB    108032            // float [2][5][8]  x double buffer         320
#define SMEM_BYTES 108352

// partial-sum buffer strides (floats); chunk stride padded (1040 % 32 == 16)
// so the updater's 8-lane groups land on disjoint banks.
#define P_CHUNK  1040
#define P_KH     2080

__device__ __forceinline__ unsigned long long ffma2(unsigned long long a,
                                                    unsigned long long b,
                                                    unsigned long long c) {
    unsigned long long d;
    asm("fma.rn.f32x2 %0, %1, %2, %3;" : "=l"(d) : "l"(a), "l"(b), "l"(c));
    return d;
}

__device__ __forceinline__ float sigf(float x) {
    return __fdividef(1.0f, 1.0f + __expf(-x));
}
__device__ __forceinline__ float tanh_fast(float x) {
    return __fdividef(2.0f, 1.0f + __expf(-2.0f * x)) - 1.0f;
}

__global__ void __launch_bounds__(THREADS)
lstm_fused_kernel(const float* __restrict__ x,
                  const float* __restrict__ Wih0, const float* __restrict__ Whh0,
                  const float* __restrict__ bih0, const float* __restrict__ bhh0,
                  const float* __restrict__ Wih1, const float* __restrict__ Whh1,
                  const float* __restrict__ bih1, const float* __restrict__ bhh1,
                  const float* __restrict__ Wfc,  const float* __restrict__ bfc,
                  float* __restrict__ out)
{
    extern __shared__ char smem[];
    float2* W1f = (float2*)(smem + OFF_W1);
    float*  WX  = (float*) (smem + OFF_WX);
    float*  HCf = (float*) (smem + OFF_HC);
    float*  PAf = (float*) (smem + OFF_PA);
    float*  PBf = (float*) (smem + OFF_PB);
    float*  XB  = (float*) (smem + OFF_XB);
    const unsigned long long* W1u = (const unsigned long long*)(smem + OFF_W1);
    const ulonglong2*         HCu = (const ulonglong2*)        (smem + OFF_HC);
    const unsigned long long* HCl = (const unsigned long long*)(smem + OFF_HC);

    const int tid = threadIdx.x;
    const int g   = tid & 255;          // gate index
    const int kh  = tid >> 8;           // k-half (0 or 1)
    const int b0  = blockIdx.x * BTILE;

    // ---- Layer-2 weights for this (gate, k-half) -> 64 REGISTERS ----
    // kh=0: Wih1 pairs (input = h1, kp 0..31); kh=1: Whh1 pairs (rec = h2, kp 32..63)
    unsigned long long w2r[32];
    {
        const float* wbase = (kh == 0) ? Wih1 : Whh1;
        const unsigned long long* ws =
            (const unsigned long long*)(wbase + (size_t)g * HH);
        #pragma unroll
        for (int k = 0; k < 32; k++) w2r[k] = ws[k];
    }

    // ---- Stage layer-1 weights into SMEM ----
    for (int i = tid; i < GG * (HH / 2); i += THREADS) {
        int gg = i >> 5, kp = i & 31;
        W1f[kp * GG + gg] = ((const float2*)Whh0)[i];
    }
    for (int i = tid; i < GG * DD; i += THREADS) {
        int gg = i / DD, d = i - gg * DD;
        WX[d * GG + gg] = Wih0[i];
    }
    for (int i = tid; i < 64 * 8 * 2; i += THREADS) HCf[i] = 0.0f;   // h1,h2

    const float breg1 = bih0[g] + bhh0[g];
    const float breg2 = bih1[g] + bhh1[g];

    // initial x staging for t=0
    const int bb = tid / DD, dd = tid - (tid / DD) * DD;   // valid when tid<35
    if (tid < DD * BTILE) {
        int bidx = b0 + bb; if (bidx >= BB) bidx = BB - 1;
        XB[dd * 8 + bb] = x[((size_t)bidx * TT + 0) * DD + dd];
    }
    __syncthreads();

    // ---- updater mapping: all 512 threads -> unit uu in [0,64), batch ub in [0,8) ----
    // (FIX vs. previous round: no tid<448 cap; units 56..63 are now updated.)
    const int uu  = tid >> 3;
    const int ub  = tid & 7;
    const bool upd = (ub < 7);
    const int hco1 = (uu >> 1) * 16 + ub * 2 + (uu & 1);     // h1 slot (floats)
    const int cb   = (ub >> 2) * P_CHUNK;                    // chunk offset
    const int bbm  = ub & 3;
    float c1 = 0.0f, c2 = 0.0f;

    const int kpbase = kh * 16;        // layer-1 kp range for this half

    for (int t = 0; t < TT; ++t) {
        const int cur = t & 1, nxt = cur ^ 1;

        // prefetch next x into regs (hidden behind A-accum)
        float xpre = 0.0f;
        if (tid < DD * BTILE) {
            int tn = (t + 1 < TT) ? (t + 1) : t;
            int bidx = b0 + bb; if (bidx >= BB) bidx = BB - 1;
            xpre = x[((size_t)bidx * TT + tn) * DD + dd];
        }

        // ================= Phase A-accum: layer-1 partial GEMV =================
        unsigned long long acc[BTILE];
        if (kh == 0) {
            float sx[BTILE];
            #pragma unroll
            for (int b = 0; b < BTILE; b++) sx[b] = breg1;
            const float* xrow = XB + cur * 40;
            #pragma unroll
            for (int d = 0; d < DD; d++) {
                float  w  = WX[d * GG + g];
                float4 xa = *(const float4*)(xrow + d * 8);
                float4 xc = *(const float4*)(xrow + d * 8 + 4);
                sx[0] += w * xa.x; sx[1] += w * xa.y; sx[2] += w * xa.z; sx[3] += w * xa.w;
                sx[4] += w * xc.x; sx[5] += w * xc.y; sx[6] += w * xc.z;
            }
            #pragma unroll
            for (int b = 0; b < BTILE; b++)
                acc[b] = (unsigned long long)__float_as_uint(sx[b]);
        } else {
            #pragma unroll
            for (int b = 0; b < BTILE; b++) acc[b] = 0ull;
        }

        #pragma unroll
        for (int kk = 0; kk < 16; kk++) {
            const int kp = kpbase + kk;
            unsigned long long w = W1u[kp * GG + g];
            ulonglong2 h01 = HCu[kp * 4 + 0];
            ulonglong2 h23 = HCu[kp * 4 + 1];
            ulonglong2 h45 = HCu[kp * 4 + 2];
            unsigned long long h6 = HCl[kp * 8 + 6];
            acc[0] = ffma2(w, h01.x, acc[0]); acc[1] = ffma2(w, h01.y, acc[1]);
            acc[2] = ffma2(w, h23.x, acc[2]); acc[3] = ffma2(w, h23.y, acc[3]);
            acc[4] = ffma2(w, h45.x, acc[4]); acc[5] = ffma2(w, h45.y, acc[5]);
            acc[6] = ffma2(w, h6,    acc[6]);
        }
        {
            float av[BTILE + 1];
            #pragma unroll
            for (int b = 0; b < BTILE; b++)
                av[b] = __uint_as_float((unsigned)acc[b]) +
                        __uint_as_float((unsigned)(acc[b] >> 32));
            av[7] = 0.0f;
            float* pbase = PAf + kh * P_KH + g * 4;
            *(float4*)(pbase)           = make_float4(av[0], av[1], av[2], av[3]);
            *(float4*)(pbase + P_CHUNK) = make_float4(av[4], av[5], av[6], av[7]);
        }
        if (tid < DD * BTILE) XB[nxt * 40 + dd * 8 + bb] = xpre;
        __syncthreads();   // bar 1

        // ================= Phase A-update: layer-1 activations + cell =================
        if (upd) {
            const float* p0 = PAf + cb + bbm;
            const float* p1 = p0 + P_KH;
            float vi = p0[(uu)       * 4] + p1[(uu)       * 4];
            float vf = p0[(64  + uu) * 4] + p1[(64  + uu) * 4];
            float vg = p0[(128 + uu) * 4] + p1[(128 + uu) * 4];
            float vo = p0[(192 + uu) * 4] + p1[(192 + uu) * 4];
            float ai = sigf(vi), af = sigf(vf), ag = tanh_fast(vg), ao = sigf(vo);
            c1 = af * c1 + ai * ag;
            HCf[hco1] = ao * tanh_fast(c1);
        }
        __syncthreads();   // bar 2

        // ================= Phase B-accum: layer-2 partial GEMV =================
        if (kh == 0) {
            #pragma unroll
            for (int b = 0; b < BTILE; b++)
                acc[b] = (unsigned long long)__float_as_uint(breg2);
        } else {
            #pragma unroll
            for (int b = 0; b < BTILE; b++) acc[b] = 0ull;
        }
        #pragma unroll
        for (int k = 0; k < 32; k++) {
            const int kp = kh * 32 + k;     // kh0 -> h1 (kp 0..31), kh1 -> h2 (kp 32..63)
            unsigned long long w = w2r[k];
            ulonglong2 h01 = HCu[kp * 4 + 0];
            ulonglong2 h23 = HCu[kp * 4 + 1];
            ulonglong2 h45 = HCu[kp * 4 + 2];
            unsigned long long h6 = HCl[kp * 8 + 6];
            acc[0] = ffma2(w, h01.x, acc[0]); acc[1] = ffma2(w, h01.y, acc[1]);
            acc[2] = ffma2(w, h23.x, acc[2]); acc[3] = ffma2(w, h23.y, acc[3]);
            acc[4] = ffma2(w, h45.x, acc[4]); acc[5] = ffma2(w, h45.y, acc[5]);
            acc[6] = ffma2(w, h6,    acc[6]);
        }
        {
            float av[BTILE + 1];
            #pragma unroll
            for (int b = 0; b < BTILE; b++)
                av[b] = __uint_as_float((unsigned)acc[b]) +
                        __uint_as_float((unsigned)(acc[b] >> 32));
            av[7] = 0.0f;
            float* pbase = PBf + kh * P_KH + g * 4;
            *(float4*)(pbase)           = make_float4(av[0], av[1], av[2], av[3]);
            *(float4*)(pbase + P_CHUNK) = make_float4(av[4], av[5], av[6], av[7]);
        }
        __syncthreads();   // bar 3

        // ================= Phase B-update: layer-2 activations + cell =================
        if (upd) {
            const float* p0 = PBf + cb + bbm;
            const float* p1 = p0 + P_KH;
            float vi = p0[(uu)       * 4] + p1[(uu)       * 4];
            float vf = p0[(64  + uu) * 4] + p1[(64  + uu) * 4];
            float vg = p0[(128 + uu) * 4] + p1[(128 + uu) * 4];
            float vo = p0[(192 + uu) * 4] + p1[(192 + uu) * 4];
            float ai = sigf(vi), af = sigf(vf), ag = tanh_fast(vg), ao = sigf(vo);
            c2 = af * c2 + ai * ag;
            HCf[512 + hco1] = ao * tanh_fast(c2);
        }
        // no bar here: next A-accum touches neither h2 nor PB; stragglers
        // rejoin at bar 1 before anyone reads PA or h1.
    }
    __syncthreads();

    // ========= Fused FC + ReLU: out[b][o] = relu(h2[b] . Wfc[o] + bfc[o]) =========
    if (tid < 32 * BTILE) {
        const int b  = tid >> 5;
        const int o  = (tid & 31) * 4;
        const int bidx = b0 + b;
        if (bidx < BB) {
            const float* w0 = Wfc + (size_t)(o + 0) * HH;
            const float* w1 = Wfc + (size_t)(o + 1) * HH;
            const float* w2 = Wfc + (size_t)(o + 2) * HH;
            const float* w3 = Wfc + (size_t)(o + 3) * HH;
            float s0 = bfc[o], s1 = bfc[o + 1], s2 = bfc[o + 2], s3 = bfc[o + 3];
            #pragma unroll
            for (int u = 0; u < HH; u++) {
                float h = HCf[512 + (u >> 1) * 16 + b * 2 + (u & 1)];
                s0 += h * w0[u]; s1 += h * w1[u]; s2 += h * w2[u]; s3 += h * w3[u];
            }
            float4 r = make_float4(fmaxf(s0, 0.f), fmaxf(s1, 0.f),
                                   fmaxf(s2, 0.f), fmaxf(s3, 0.f));
            *(float4*)(out + (size_t)bidx * OUTN + o) = r;
        }
    }
}

extern "C" void kernel_launch(void* const* d_in, const int* in_sizes, int n_in,
                              void* d_out, int out_size)
{
    const float* x    = (const float*)d_in[0];
    const float* Wih0 = (const float*)d_in[1];
    const float* Whh0 = (const float*)d_in[2];
    const float* bih0 = (const float*)d_in[3];
    const float* bhh0 = (const float*)d_in[4];
    const float* Wih1 = (const float*)d_in[5];
    const float* Whh1 = (const float*)d_in[6];
    const float* bih1 = (const float*)d_in[7];
    const float* bhh1 = (const float*)d_in[8];
    const float* Wfc  = (const float*)d_in[9];
    const float* bfc  = (const float*)d_in[10];
    float* out = (float*)d_out;

    cudaFuncSetAttribute(lstm_fused_kernel,
                         cudaFuncAttributeMaxDynamicSharedMemorySize, SMEM_BYTES);

    lstm_fused_kernel<<<NCTA, THREADS, SMEM_BYTES>>>(
        x, Wih0, Whh0, bih0, bhh0, Wih1, Whh1, bih1, bhh1, Wfc, bfc, out);
}

// round 12
// speedup vs baseline: 1.4404x; 1.0181x over previous
#include <cuda_runtime.h>

// Problem constants
#define BB     1024
#define TT     2048
#define DD     5
#define HH     64
#define GG     256     // 4*H gates
#define OUTN   128
#define BTILE  7
#define THREADS 512
#define NCTA   147     // 147*7 = 1029 >= 1024 (last CTA: 2 valid, 5 dummy)

// Shared memory layout (bytes)
#define OFF_W1    0                 // float2[32][256]  Whh0 k-pairs          65536
#define OFF_WX    65536             // float [5][256]   Wih0 transposed        5120
#define OFF_HC    70656             // float2[64][8]    kp0-31: h1, kp32-63: h2 4096
#define OFF_PA    74752             // float[2][2 chunks][1040] layer-1 partials 16640
#define OFF_PB    91392             // same for layer-2                       16640
#define OFF_XB    108032            // float [2][5][8]  x double buffer         320
#define SMEM_BYTES 108352

// partial-sum buffer strides (floats); chunk stride padded (1040 % 32 == 16)
// so the updater's 8-lane groups land on disjoint banks.
#define P_CHUNK  1040
#define P_KH     2080

__device__ __forceinline__ unsigned long long ffma2(unsigned long long a,
                                                    unsigned long long b,
                                                    unsigned long long c) {
    unsigned long long d;
    asm("fma.rn.f32x2 %0, %1, %2, %3;" : "=l"(d) : "l"(a), "l"(b), "l"(c));
    return d;
}

__device__ __forceinline__ float sigf(float x) {
    return __fdividef(1.0f, 1.0f + __expf(-x));
}
__device__ __forceinline__ float tanh_fast(float x) {
    return __fdividef(2.0f, 1.0f + __expf(-2.0f * x)) - 1.0f;
}

__global__ void __launch_bounds__(THREADS)
lstm_fused_kernel(const float* __restrict__ x,
                  const float* __restrict__ Wih0, const float* __restrict__ Whh0,
                  const float* __restrict__ bih0, const float* __restrict__ bhh0,
                  const float* __restrict__ Wih1, const float* __restrict__ Whh1,
                  const float* __restrict__ bih1, const float* __restrict__ bhh1,
                  const float* __restrict__ Wfc,  const float* __restrict__ bfc,
                  float* __restrict__ out)
{
    extern __shared__ char smem[];
    float2* W1f = (float2*)(smem + OFF_W1);
    float*  WX  = (float*) (smem + OFF_WX);
    float*  HCf = (float*) (smem + OFF_HC);
    float*  PAf = (float*) (smem + OFF_PA);
    float*  PBf = (float*) (smem + OFF_PB);
    float*  XB  = (float*) (smem + OFF_XB);
    const unsigned long long* W1u = (const unsigned long long*)(smem + OFF_W1);
    const ulonglong2*         HCu = (const ulonglong2*)        (smem + OFF_HC);
    const unsigned long long* HCl = (const unsigned long long*)(smem + OFF_HC);

    const int tid = threadIdx.x;
    const int g   = tid & 255;          // gate index
    const int kh  = tid >> 8;           // k-half (0 or 1)
    const int b0  = blockIdx.x * BTILE;

    // ---- Layer-2 weights for this (gate, k-half) -> 64 REGISTERS ----
    unsigned long long w2r[32];
    {
        const float* wbase = (kh == 0) ? Wih1 : Whh1;
        const unsigned long long* ws =
            (const unsigned long long*)(wbase + (size_t)g * HH);
        #pragma unroll
        for (int k = 0; k < 32; k++) w2r[k] = ws[k];
    }

    // ---- Stage layer-1 weights into SMEM ----
    for (int i = tid; i < GG * (HH / 2); i += THREADS) {
        int gg = i >> 5, kp = i & 31;
        W1f[kp * GG + gg] = ((const float2*)Whh0)[i];
    }
    for (int i = tid; i < GG * DD; i += THREADS) {
        int gg = i / DD, d = i - gg * DD;
        WX[d * GG + gg] = Wih0[i];
    }
    for (int i = tid; i < 64 * 8 * 2; i += THREADS) HCf[i] = 0.0f;   // h1,h2

    const float breg1 = bih0[g] + bhh0[g];
    const float breg2 = bih1[g] + bhh1[g];

    // initial x staging for iteration 0 (reads x(0))
    const int bb = tid / DD, dd = tid - (tid / DD) * DD;   // valid when tid<35
    if (tid < DD * BTILE) {
        int bidx = b0 + bb; if (bidx >= BB) bidx = BB - 1;
        XB[dd * 8 + bb] = x[((size_t)bidx * TT + 0) * DD + dd];
    }
    __syncthreads();

    // ---- updater mapping: all 512 threads -> unit uu in [0,64), batch ub in [0,8) ----
    const int uu  = tid >> 3;
    const int ub  = tid & 7;
    const bool upd = (ub < 7);
    const int hco1 = (uu >> 1) * 16 + ub * 2 + (uu & 1);     // h1 slot (floats)
    const int cb   = (ub >> 2) * P_CHUNK;                    // chunk offset
    const int bbm  = ub & 3;
    float c1 = 0.0f, c2 = 0.0f;

    const int kpbase = kh * 16;        // layer-1 kp range for this half

    // ===================== Pipelined recurrence =====================
    // iter j:   ACC: gates1(j)   <- h1(j-1), x(j)        (PA)
    //                gates2(j-1) <- h1(j-1), h2(j-2)     (PB)
    //           bar
    //           UPD: h1(j) <- PA ;  if (j>0) h2(j-1) <- PB
    //           bar
    // Layer 2 lags one step; loop runs TT+1 iterations.
    for (int j = 0; j <= TT; ++j) {
        const int cur = j & 1, nxt = cur ^ 1;

        // prefetch x(j+1) into regs (hidden behind the big ACC phase)
        float xpre = 0.0f;
        if (tid < DD * BTILE) {
            int tn = (j + 1 < TT) ? (j + 1) : (TT - 1);
            int bidx = b0 + bb; if (bidx >= BB) bidx = BB - 1;
            xpre = x[((size_t)bidx * TT + tn) * DD + dd];
        }

        // ---------- A-accum: layer-1 partial GEMV (gates1(j)) ----------
        unsigned long long acc[BTILE];
        if (kh == 0) {
            float sx[BTILE];
            #pragma unroll
            for (int b = 0; b < BTILE; b++) sx[b] = breg1;
            const float* xrow = XB + cur * 40;
            #pragma unroll
            for (int d = 0; d < DD; d++) {
                float  w  = WX[d * GG + g];
                float4 xa = *(const float4*)(xrow + d * 8);
                float4 xc = *(const float4*)(xrow + d * 8 + 4);
                sx[0] += w * xa.x; sx[1] += w * xa.y; sx[2] += w * xa.z; sx[3] += w * xa.w;
                sx[4] += w * xc.x; sx[5] += w * xc.y; sx[6] += w * xc.z;
            }
            #pragma unroll
            for (int b = 0; b < BTILE; b++)
                acc[b] = (unsigned long long)__float_as_uint(sx[b]);
        } else {
            #pragma unroll
            for (int b = 0; b < BTILE; b++) acc[b] = 0ull;
        }

        #pragma unroll
        for (int kk = 0; kk < 16; kk++) {
            const int kp = kpbase + kk;
            unsigned long long w = W1u[kp * GG + g];
            ulonglong2 h01 = HCu[kp * 4 + 0];
            ulonglong2 h23 = HCu[kp * 4 + 1];
            ulonglong2 h45 = HCu[kp * 4 + 2];
            unsigned long long h6 = HCl[kp * 8 + 6];
            acc[0] = ffma2(w, h01.x, acc[0]); acc[1] = ffma2(w, h01.y, acc[1]);
            acc[2] = ffma2(w, h23.x, acc[2]); acc[3] = ffma2(w, h23.y, acc[3]);
            acc[4] = ffma2(w, h45.x, acc[4]); acc[5] = ffma2(w, h45.y, acc[5]);
            acc[6] = ffma2(w, h6,    acc[6]);
        }
        {
            float av[BTILE + 1];
            #pragma unroll
            for (int b = 0; b < BTILE; b++)
                av[b] = __uint_as_float((unsigned)acc[b]) +
                        __uint_as_float((unsigned)(acc[b] >> 32));
            av[7] = 0.0f;
            float* pbase = PAf + kh * P_KH + g * 4;
            *(float4*)(pbase)           = make_float4(av[0], av[1], av[2], av[3]);
            *(float4*)(pbase + P_CHUNK) = make_float4(av[4], av[5], av[6], av[7]);
        }

        // ---------- B-accum: layer-2 partial GEMV (gates2(j-1)) ----------
        // reads h1(j-1) (slots 0..31) and h2(j-2) (slots 32..63) -- same
        // HC state A just read; no barrier needed in between.
        if (kh == 0) {
            #pragma unroll
            for (int b = 0; b < BTILE; b++)
                acc[b] = (unsigned long long)__float_as_uint(breg2);
        } else {
            #pragma unroll
            for (int b = 0; b < BTILE; b++) acc[b] = 0ull;
        }
        #pragma unroll
        for (int k = 0; k < 32; k++) {
            const int kp = kh * 32 + k;
            unsigned long long w = w2r[k];
            ulonglong2 h01 = HCu[kp * 4 + 0];
            ulonglong2 h23 = HCu[kp * 4 + 1];
            ulonglong2 h45 = HCu[kp * 4 + 2];
            unsigned long long h6 = HCl[kp * 8 + 6];
            acc[0] = ffma2(w, h01.x, acc[0]); acc[1] = ffma2(w, h01.y, acc[1]);
            acc[2] = ffma2(w, h23.x, acc[2]); acc[3] = ffma2(w, h23.y, acc[3]);
            acc[4] = ffma2(w, h45.x, acc[4]); acc[5] = ffma2(w, h45.y, acc[5]);
            acc[6] = ffma2(w, h6,    acc[6]);
        }
        {
            float av[BTILE + 1];
            #pragma unroll
            for (int b = 0; b < BTILE; b++)
                av[b] = __uint_as_float((unsigned)acc[b]) +
                        __uint_as_float((unsigned)(acc[b] >> 32));
            av[7] = 0.0f;
            float* pbase = PBf + kh * P_KH + g * 4;
            *(float4*)(pbase)           = make_float4(av[0], av[1], av[2], av[3]);
            *(float4*)(pbase + P_CHUNK) = make_float4(av[4], av[5], av[6], av[7]);
        }
        if (tid < DD * BTILE) XB[nxt * 40 + dd * 8 + bb] = xpre;
        __syncthreads();   // bar 1: PA/PB/XB published; h reads complete

        // ---------- UPD: both layers' activations + cell updates ----------
        if (upd) {
            // layer 1 -> h1(j)
            {
                const float* p0 = PAf + cb + bbm;
                const float* p1 = p0 + P_KH;
                float vi = p0[(uu)       * 4] + p1[(uu)       * 4];
                float vf = p0[(64  + uu) * 4] + p1[(64  + uu) * 4];
                float vg = p0[(128 + uu) * 4] + p1[(128 + uu) * 4];
                float vo = p0[(192 + uu) * 4] + p1[(192 + uu) * 4];
                float ai = sigf(vi), af = sigf(vf), ag = tanh_fast(vg), ao = sigf(vo);
                c1 = af * c1 + ai * ag;
                HCf[hco1] = ao * tanh_fast(c1);
            }
            // layer 2 -> h2(j-1); at j==0 gates are bias-garbage, keep h2=0
            if (j > 0) {
                const float* p0 = PBf + cb + bbm;
                const float* p1 = p0 + P_KH;
                float vi = p0[(uu)       * 4] + p1[(uu)       * 4];
                float vf = p0[(64  + uu) * 4] + p1[(64  + uu) * 4];
                float vg = p0[(128 + uu) * 4] + p1[(128 + uu) * 4];
                float vo = p0[(192 + uu) * 4] + p1[(192 + uu) * 4];
                float ai = sigf(vi), af = sigf(vf), ag = tanh_fast(vg), ao = sigf(vo);
                c2 = af * c2 + ai * ag;
                HCf[512 + hco1] = ao * tanh_fast(c2);
            }
        }
        __syncthreads();   // bar 2: h1/h2 published for next ACC
    }

    // ========= Fused FC + ReLU: out[b][o] = relu(h2[b] . Wfc[o] + bfc[o]) =========
    if (tid < 32 * BTILE) {
        const int b  = tid >> 5;
        const int o  = (tid & 31) * 4;
        const int bidx = b0 + b;
        if (bidx < BB) {
            const float* w0 = Wfc + (size_t)(o + 0) * HH;
            const float* w1 = Wfc + (size_t)(o + 1) * HH;
            const float* w2 = Wfc + (size_t)(o + 2) * HH;
            const float* w3 = Wfc + (size_t)(o + 3) * HH;
            float s0 = bfc[o], s1 = bfc[o + 1], s2 = bfc[o + 2], s3 = bfc[o + 3];
            #pragma unroll
            for (int u = 0; u < HH; u++) {
                float h = HCf[512 + (u >> 1) * 16 + b * 2 + (u & 1)];
                s0 += h * w0[u]; s1 += h * w1[u]; s2 += h * w2[u]; s3 += h * w3[u];
            }
            float4 r = make_float4(fmaxf(s0, 0.f), fmaxf(s1, 0.f),
                                   fmaxf(s2, 0.f), fmaxf(s3, 0.f));
            *(float4*)(out + (size_t)bidx * OUTN + o) = r;
        }
    }
}

extern "C" void kernel_launch(void* const* d_in, const int* in_sizes, int n_in,
                              void* d_out, int out_size)
{
    const float* x    = (const float*)d_in[0];
    const float* Wih0 = (const float*)d_in[1];
    const float* Whh0 = (const float*)d_in[2];
    const float* bih0 = (const float*)d_in[3];
    const float* bhh0 = (const float*)d_in[4];
    const float* Wih1 = (const float*)d_in[5];
    const float* Whh1 = (const float*)d_in[6];
    const float* bih1 = (const float*)d_in[7];
    const float* bhh1 = (const float*)d_in[8];
    const float* Wfc  = (const float*)d_in[9];
    const float* bfc  = (const float*)d_in[10];
    float* out = (float*)d_out;

    cudaFuncSetAttribute(lstm_fused_kernel,
                         cudaFuncAttributeMaxDynamicSharedMemorySize, SMEM_BYTES);

    lstm_fused_kernel<<<NCTA, THREADS, SMEM_BYTES>>>(
        x, Wih0, Whh0, bih0, bhh0, Wih1, Whh1, bih1, bhh1, Wfc, bfc, out);
}

// round 13
// speedup vs baseline: 1.8092x; 1.2561x over previous
#include <cuda_runtime.h>

// Problem constants
#define BB     1024
#define TT     2048
#define DD     5
#define HH     64
#define GG     256     // 4*H gates
#define OUTN   128
#define BTILE  7
#define THREADS 512
#define NCTA   147     // 147*7 = 1029 >= 1024 (last CTA: 2 valid, 5 dummy)

// Shared memory layout (bytes)
#define OFF_W1    0                 // float2[32][256]  Whh0 k-pairs          65536
#define OFF_WX    65536             // float [5][256]   Wih0 transposed        5120
#define OFF_HC    70656             // float2[64][8]    kp0-31: h1, kp32-63: h2 4096
#define OFF_PA    74752             // float[2][2 chunks][1040] layer-1 partials 16640
#define OFF_PB    91392             // same for layer-2                       16640
#define OFF_XB    108032            // float [2][5][8]  x double buffer         320
#define SMEM_BYTES 108352

// partial-sum buffer strides (floats); chunk stride padded (1040 % 32 == 16)
// so the updater's 8-lane groups land on disjoint banks.
#define P_CHUNK  1040
#define P_KH     2080

__device__ __forceinline__ unsigned long long ffma2(unsigned long long a,
                                                    unsigned long long b,
                                                    unsigned long long c) {
    unsigned long long d;
    asm("fma.rn.f32x2 %0, %1, %2, %3;" : "=l"(d) : "l"(a), "l"(b), "l"(c));
    return d;
}

__device__ __forceinline__ float sigf(float x) {
    return __fdividef(1.0f, 1.0f + __expf(-x));
}
__device__ __forceinline__ float tanh_fast(float x) {
    return __fdividef(2.0f, 1.0f + __expf(-2.0f * x)) - 1.0f;
}

__global__ void __launch_bounds__(THREADS)
lstm_fused_kernel(const float* __restrict__ x,
                  const float* __restrict__ Wih0, const float* __restrict__ Whh0,
                  const float* __restrict__ bih0, const float* __restrict__ bhh0,
                  const float* __restrict__ Wih1, const float* __restrict__ Whh1,
                  const float* __restrict__ bih1, const float* __restrict__ bhh1,
                  const float* __restrict__ Wfc,  const float* __restrict__ bfc,
                  float* __restrict__ out)
{
    extern __shared__ char smem[];
    float2* W1f = (float2*)(smem + OFF_W1);
    float*  WX  = (float*) (smem + OFF_WX);
    float*  HCf = (float*) (smem + OFF_HC);
    float*  PAf = (float*) (smem + OFF_PA);
    float*  PBf = (float*) (smem + OFF_PB);
    float*  XB  = (float*) (smem + OFF_XB);
    const unsigned long long* W1u = (const unsigned long long*)(smem + OFF_W1);
    const ulonglong2*         HCu = (const ulonglong2*)        (smem + OFF_HC);
    const unsigned long long* HCl = (const unsigned long long*)(smem + OFF_HC);

    const int tid = threadIdx.x;
    const int g   = tid & 255;          // gate index
    const int kh  = tid >> 8;           // k-half (0 or 1)
    const int b0  = blockIdx.x * BTILE;
    const int kpbase = kh * 16;         // this thread's 16-kp slice (both layers)

    // ---- Layer-2 weights for this (gate, k-slice) -> 64 REGISTERS ----
    // w2r[0..15]  = Wih1 pairs for h1 kp [kpbase, kpbase+16)
    // w2r[16..31] = Whh1 pairs for h2 kp [kpbase, kpbase+16)  (HC slots 32+kp)
    unsigned long long w2r[32];
    {
        const unsigned long long* wi =
            (const unsigned long long*)(Wih1 + (size_t)g * HH);
        const unsigned long long* wh =
            (const unsigned long long*)(Whh1 + (size_t)g * HH);
        #pragma unroll
        for (int k = 0; k < 16; k++) w2r[k]      = wi[kpbase + k];
        #pragma unroll
        for (int k = 0; k < 16; k++) w2r[16 + k] = wh[kpbase + k];
    }

    // ---- Stage layer-1 weights into SMEM ----
    for (int i = tid; i < GG * (HH / 2); i += THREADS) {
        int gg = i >> 5, kp = i & 31;
        W1f[kp * GG + gg] = ((const float2*)Whh0)[i];
    }
    for (int i = tid; i < GG * DD; i += THREADS) {
        int gg = i / DD, d = i - gg * DD;
        WX[d * GG + gg] = Wih0[i];
    }
    for (int i = tid; i < 64 * 8 * 2; i += THREADS) HCf[i] = 0.0f;   // h1,h2

    const float breg1 = bih0[g] + bhh0[g];
    const float breg2 = bih1[g] + bhh1[g];

    // initial x staging for iteration 0 (reads x(0))
    const int bb = tid / DD, dd = tid - (tid / DD) * DD;   // valid when tid<35
    if (tid < DD * BTILE) {
        int bidx = b0 + bb; if (bidx >= BB) bidx = BB - 1;
        XB[dd * 8 + bb] = x[((size_t)bidx * TT + 0) * DD + dd];
    }
    __syncthreads();

    // ---- updater mapping: all 512 threads -> unit uu in [0,64), batch ub in [0,8) ----
    const int uu  = tid >> 3;
    const int ub  = tid & 7;
    const bool upd = (ub < 7);
    const int hco1 = (uu >> 1) * 16 + ub * 2 + (uu & 1);     // h1 slot (floats)
    const int cb   = (ub >> 2) * P_CHUNK;                    // chunk offset
    const int bbm  = ub & 3;
    float c1 = 0.0f, c2 = 0.0f;

    // ===================== Pipelined recurrence =====================
    // iter j:   ACC (fused): gates1(j) += Whh0 . h1(j-1)      [A, SMEM weights]
    //                        gates2(j-1) += Wih1 . h1(j-1)    [B, reg weights,
    //                                                          SAME h loads as A]
    //                        gates2(j-1) += Whh1 . h2(j-2)    [B, reg weights]
    //           bar ; UPD: h1(j) <- PA ; if (j>0) h2(j-1) <- PB ; bar
    for (int j = 0; j <= TT; ++j) {
        const int cur = j & 1, nxt = cur ^ 1;

        // prefetch x(j+1) into regs (hidden behind the ACC phase)
        float xpre = 0.0f;
        if (tid < DD * BTILE) {
            int tn = (j + 1 < TT) ? (j + 1) : (TT - 1);
            int bidx = b0 + bb; if (bidx >= BB) bidx = BB - 1;
            xpre = x[((size_t)bidx * TT + tn) * DD + dd];
        }

        // ---------- accA init: bias + Wx.x(j) on kh0 ----------
        unsigned long long accA[BTILE];
        if (kh == 0) {
            float sx[BTILE];
            #pragma unroll
            for (int b = 0; b < BTILE; b++) sx[b] = breg1;
            const float* xrow = XB + cur * 40;
            #pragma unroll
            for (int d = 0; d < DD; d++) {
                float  w  = WX[d * GG + g];
                float4 xa = *(const float4*)(xrow + d * 8);
                float4 xc = *(const float4*)(xrow + d * 8 + 4);
                sx[0] += w * xa.x; sx[1] += w * xa.y; sx[2] += w * xa.z; sx[3] += w * xa.w;
                sx[4] += w * xc.x; sx[5] += w * xc.y; sx[6] += w * xc.z;
            }
            #pragma unroll
            for (int b = 0; b < BTILE; b++)
                accA[b] = (unsigned long long)__float_as_uint(sx[b]);
        } else {
            #pragma unroll
            for (int b = 0; b < BTILE; b++) accA[b] = 0ull;
        }

        unsigned long long accB[BTILE];
        if (kh == 0) {
            #pragma unroll
            for (int b = 0; b < BTILE; b++)
                accB[b] = (unsigned long long)__float_as_uint(breg2);
        } else {
            #pragma unroll
            for (int b = 0; b < BTILE; b++) accB[b] = 0ull;
        }

        // ---------- FUSED loop over h1 kp slice: one h load, two FFMA streams ----------
        #pragma unroll
        for (int kk = 0; kk < 16; kk++) {
            const int kp = kpbase + kk;
            unsigned long long wA = W1u[kp * GG + g];
            unsigned long long wB = w2r[kk];
            ulonglong2 h01 = HCu[kp * 4 + 0];
            ulonglong2 h23 = HCu[kp * 4 + 1];
            ulonglong2 h45 = HCu[kp * 4 + 2];
            unsigned long long h6 = HCl[kp * 8 + 6];
            accA[0] = ffma2(wA, h01.x, accA[0]); accB[0] = ffma2(wB, h01.x, accB[0]);
            accA[1] = ffma2(wA, h01.y, accA[1]); accB[1] = ffma2(wB, h01.y, accB[1]);
            accA[2] = ffma2(wA, h23.x, accA[2]); accB[2] = ffma2(wB, h23.x, accB[2]);
            accA[3] = ffma2(wA, h23.y, accA[3]); accB[3] = ffma2(wB, h23.y, accB[3]);
            accA[4] = ffma2(wA, h45.x, accA[4]); accB[4] = ffma2(wB, h45.x, accB[4]);
            accA[5] = ffma2(wA, h45.y, accA[5]); accB[5] = ffma2(wB, h45.y, accB[5]);
            accA[6] = ffma2(wA, h6,    accA[6]); accB[6] = ffma2(wB, h6,    accB[6]);
        }
        // publish layer-1 partials (accA dead afterwards -> frees registers)
        {
            float av[BTILE + 1];
            #pragma unroll
            for (int b = 0; b < BTILE; b++)
                av[b] = __uint_as_float((unsigned)accA[b]) +
                        __uint_as_float((unsigned)(accA[b] >> 32));
            av[7] = 0.0f;
            float* pbase = PAf + kh * P_KH + g * 4;
            *(float4*)(pbase)           = make_float4(av[0], av[1], av[2], av[3]);
            *(float4*)(pbase + P_CHUNK) = make_float4(av[4], av[5], av[6], av[7]);
        }

        // ---------- B-only loop over h2 kp slice ----------
        #pragma unroll
        for (int kk = 0; kk < 16; kk++) {
            const int kp = 32 + kpbase + kk;     // h2 region in HC
            unsigned long long wB = w2r[16 + kk];
            ulonglong2 h01 = HCu[kp * 4 + 0];
            ulonglong2 h23 = HCu[kp * 4 + 1];
            ulonglong2 h45 = HCu[kp * 4 + 2];
            unsigned long long h6 = HCl[kp * 8 + 6];
            accB[0] = ffma2(wB, h01.x, accB[0]); accB[1] = ffma2(wB, h01.y, accB[1]);
            accB[2] = ffma2(wB, h23.x, accB[2]); accB[3] = ffma2(wB, h23.y, accB[3]);
            accB[4] = ffma2(wB, h45.x, accB[4]); accB[5] = ffma2(wB, h45.y, accB[5]);
            accB[6] = ffma2(wB, h6,    accB[6]);
        }
        {
            float av[BTILE + 1];
            #pragma unroll
            for (int b = 0; b < BTILE; b++)
                av[b] = __uint_as_float((unsigned)accB[b]) +
                        __uint_as_float((unsigned)(accB[b] >> 32));
            av[7] = 0.0f;
            float* pbase = PBf + kh * P_KH + g * 4;
            *(float4*)(pbase)           = make_float4(av[0], av[1], av[2], av[3]);
            *(float4*)(pbase + P_CHUNK) = make_float4(av[4], av[5], av[6], av[7]);
        }
        if (tid < DD * BTILE) XB[nxt * 40 + dd * 8 + bb] = xpre;
        __syncthreads();   // bar 1: PA/PB/XB published; h reads complete

        // ---------- UPD: both layers' activations + cell updates ----------
        if (upd) {
            // layer 1 -> h1(j)
            {
                const float* p0 = PAf + cb + bbm;
                const float* p1 = p0 + P_KH;
                float vi = p0[(uu)       * 4] + p1[(uu)       * 4];
                float vf = p0[(64  + uu) * 4] + p1[(64  + uu) * 4];
                float vg = p0[(128 + uu) * 4] + p1[(128 + uu) * 4];
                float vo = p0[(192 + uu) * 4] + p1[(192 + uu) * 4];
                float ai = sigf(vi), af = sigf(vf), ag = tanh_fast(vg), ao = sigf(vo);
                c1 = af * c1 + ai * ag;
                HCf[hco1] = ao * tanh_fast(c1);
            }
            // layer 2 -> h2(j-1); at j==0 gates are bias-garbage, keep h2=0
            if (j > 0) {
                const float* p0 = PBf + cb + bbm;
                const float* p1 = p0 + P_KH;
                float vi = p0[(uu)       * 4] + p1[(uu)       * 4];
                float vf = p0[(64  + uu) * 4] + p1[(64  + uu) * 4];
                float vg = p0[(128 + uu) * 4] + p1[(128 + uu) * 4];
                float vo = p0[(192 + uu) * 4] + p1[(192 + uu) * 4];
                float ai = sigf(vi), af = sigf(vf), ag = tanh_fast(vg), ao = sigf(vo);
                c2 = af * c2 + ai * ag;
                HCf[512 + hco1] = ao * tanh_fast(c2);
            }
        }
        __syncthreads();   // bar 2: h1/h2 published for next ACC
    }

    // ========= Fused FC + ReLU: out[b][o] = relu(h2[b] . Wfc[o] + bfc[o]) =========
    if (tid < 32 * BTILE) {
        const int b  = tid >> 5;
        const int o  = (tid & 31) * 4;
        const int bidx = b0 + b;
        if (bidx < BB) {
            const float* w0 = Wfc + (size_t)(o + 0) * HH;
            const float* w1 = Wfc + (size_t)(o + 1) * HH;
            const float* w2 = Wfc + (size_t)(o + 2) * HH;
            const float* w3 = Wfc + (size_t)(o + 3) * HH;
            float s0 = bfc[o], s1 = bfc[o + 1], s2 = bfc[o + 2], s3 = bfc[o + 3];
            #pragma unroll
            for (int u = 0; u < HH; u++) {
                float h = HCf[512 + (u >> 1) * 16 + b * 2 + (u & 1)];
                s0 += h * w0[u]; s1 += h * w1[u]; s2 += h * w2[u]; s3 += h * w3[u];
            }
            float4 r = make_float4(fmaxf(s0, 0.f), fmaxf(s1, 0.f),
                                   fmaxf(s2, 0.f), fmaxf(s3, 0.f));
            *(float4*)(out + (size_t)bidx * OUTN + o) = r;
        }
    }
}

extern "C" void kernel_launch(void* const* d_in, const int* in_sizes, int n_in,
                              void* d_out, int out_size)
{
    const float* x    = (const float*)d_in[0];
    const float* Wih0 = (const float*)d_in[1];
    const float* Whh0 = (const float*)d_in[2];
    const float* bih0 = (const float*)d_in[3];
    const float* bhh0 = (const float*)d_in[4];
    const float* Wih1 = (const float*)d_in[5];
    const float* Whh1 = (const float*)d_in[6];
    const float* bih1 = (const float*)d_in[7];
    const float* bhh1 = (const float*)d_in[8];
    const float* Wfc  = (const float*)d_in[9];
    const float* bfc  = (const float*)d_in[10];
    float* out = (float*)d_out;

    cudaFuncSetAttribute(lstm_fused_kernel,
                         cudaFuncAttributeMaxDynamicSharedMemorySize, SMEM_BYTES);

    lstm_fused_kernel<<<NCTA, THREADS, SMEM_BYTES>>>(
        x, Wih0, Whh0, bih0, bhh0, Wih1, Whh1, bih1, bhh1, Wfc, bfc, out);
}